// round 14
// baseline (speedup 1.0000x reference)
#include <cuda_runtime.h>
#include <cuda_fp16.h>
#include <math.h>
#include <stdint.h>

#define Bn 8
#define Cc 32
#define Hh 256
#define Ww 256
#define HW (Hh*Ww)

// ---------------------------------------------------------------------------
// Layouts:
//  bufA (conv->scan): pair planes. plane (b*16 + c/2), word = half2(c, c+1).
//  xpk, bufB (->conv): qplanes. qplane (chunk*4 + g) holds pair-planes g and
//  g+4 of its 16-channel chunk, interleaved: words (2*px, 2*px+1).
// ---------------------------------------------------------------------------
__device__ __align__(16) uint32_t g_xpk[Bn*8*HW*2];    //  33 MB packed x (8 qplanes/b)
__device__ __align__(16) uint32_t g_bufA[Bn*16*HW];    //  33 MB conv out (16 pair planes/b)
__device__ __align__(16) uint32_t g_bufB[Bn*32*HW*2];  // 134 MB IRNN out (32 qplanes/b)
__device__ int g_ctr[8];
// fp16 weights: [ch][tap(9)][co(32)][slot(8) x half2]
__device__ __align__(16) __half g_win_h[2*9*32*16];
__device__ __align__(16) __half g_w2_h[8*9*32*16];
__device__ __align__(16) __half g_w3_h[8*9*32*16];

__device__ __forceinline__ uint32_t smem_u32(const void* p) {
    uint32_t a;
    asm("{ .reg .u64 t; cvta.to.shared.u64 t, %1; cvt.u32.u64 %0, t; }" : "=r"(a) : "l"(p));
    return a;
}
__device__ __forceinline__ void cp16(uint32_t dst, const void* src, bool pred) {
    int sz = pred ? 16 : 0;
    asm volatile("cp.async.cg.shared.global [%0], [%1], 16, %2;"
                 :: "r"(dst), "l"(src), "r"(sz) : "memory");
}
__device__ __forceinline__ void cp_commit() {
    asm volatile("cp.async.commit_group;" ::: "memory");
}
template<int N>
__device__ __forceinline__ void cp_wait() {
    asm volatile("cp.async.wait_group %0;" :: "n"(N) : "memory");
}
__device__ __forceinline__ uint32_t packh2(float a, float b) {
    __half2 h = __floats2half2_rn(a, b);
    return *reinterpret_cast<uint32_t*>(&h);
}
__device__ __forceinline__ float2 unpackh2(uint32_t w) {
    __half2 h = *reinterpret_cast<__half2*>(&w);
    return __half22float2(h);
}

// ---------------------------------------------------------------------------
// Prologue: pack x into qplanes (blocks 0..8191) + all weight preps.
// ---------------------------------------------------------------------------
__device__ void prep_w_body(const float* __restrict__ w, __half* __restrict__ wbuf,
                            int CIN, int idx)
{
    if (idx >= 32*CIN*9) return;
    int dx = idx % 3;
    int dy = (idx / 3) % 3;
    int ci = (idx / 9) % CIN;
    int co = idx / (9*CIN);
    int ch = ci >> 4, k = ci & 15;
    int p = k >> 1, hf = k & 1;
    int s = (p < 4) ? 2*p : 2*(p - 4) + 1;
    wbuf[(((ch*9 + dy*3 + dx)*32 + co)*8 + s)*2 + hf] = __float2half_rn(w[idx]);
}

__global__ void __launch_bounds__(256) prologue_kernel(
    const float* __restrict__ x, const float* __restrict__ w_in,
    const float* __restrict__ w2, const float* __restrict__ w3,
    uint32_t* __restrict__ xp, __half* __restrict__ win_h,
    __half* __restrict__ w2_h, __half* __restrict__ w3_h)
{
    int blk = blockIdx.x;
    if (blk < 8192) {
        // pack: thread = 2 pixels of one qplane
        int T = blk*256 + threadIdx.x;            // [0, 2M)
        int b = T >> 18;
        int r = T & 262143;
        int Q = r >> 15;                           // qplane 0..7 (ch = Q>>2, g = Q&3)
        int pp = r & 32767;
        int px0 = pp*2;
        int ch = Q >> 2, g = Q & 3;
        int c0 = 16*ch + 2*g;
        int c2 = c0 + 8;
        const float* xb = x + (size_t)b*32*HW + px0;
        float2 v0 = *(const float2*)(xb + (size_t)c0*HW);
        float2 v1 = *(const float2*)(xb + (size_t)(c0+1)*HW);
        float2 v2 = *(const float2*)(xb + (size_t)c2*HW);
        float2 v3 = *(const float2*)(xb + (size_t)(c2+1)*HW);
        uint4 d;
        d.x = packh2(v0.x, v1.x);
        d.y = packh2(v2.x, v3.x);
        d.z = packh2(v0.y, v1.y);
        d.w = packh2(v2.y, v3.y);
        *(uint4*)(xp + ((size_t)(b*8 + Q)*HW + px0)*2) = d;
    } else if (blk < 8192 + 144) {
        prep_w_body(w2, w2_h, 128, (blk - 8192)*256 + threadIdx.x);
    } else if (blk < 8192 + 288) {
        prep_w_body(w3, w3_h, 128, (blk - 8336)*256 + threadIdx.x);
    } else {
        prep_w_body(w_in, win_h, 32, (blk - 8480)*256 + threadIdx.x);
    }
}

// ---------------------------------------------------------------------------
// Scan bodies. Each block handles one qplane-unit = 4 channels (pair-planes
// p0 = 8c'+j and p1 = p0+4 of its direction), reading bufA pair planes and
// writing one bufB qplane. 64 H blocks + 64 W blocks per half.
// ---------------------------------------------------------------------------
__device__ void scan_body(int blk, uint32_t* xs,
    const uint32_t* __restrict__ in, uint32_t* __restrict__ outp,
    const float* __restrict__ wp, const float* __restrict__ bp, int b_base)
{
    if (blk < 64) {
        // ---- H scans ----
        int dirg = (blk >> 5) ? 0 : 2;     // 0..31 => down(2), 32..63 => up(0)
        int n = blk & 31;
        int b = b_base + (n >> 3), c1 = (n >> 2) & 1, j = n & 3;
        int p0 = 8*c1 + j, p1 = p0 + 4;
        int w = threadIdx.x;
        const uint32_t* g0 = in + ((size_t)b*16 + p0)*HW + w;
        const uint32_t* g1 = in + ((size_t)b*16 + p1)*HW + w;
        uint2* outq = (uint2*)(outp + ((size_t)(b*32 + (2*dirg + c1)*4 + j))*HW*2) + w;
        float wc00 = wp[dirg*32 + 2*p0],     bc00 = bp[dirg*32 + 2*p0];
        float wc01 = wp[dirg*32 + 2*p0 + 1], bc01 = bp[dirg*32 + 2*p0 + 1];
        float wc10 = wp[dirg*32 + 2*p1],     bc10 = bp[dirg*32 + 2*p1];
        float wc11 = wp[dirg*32 + 2*p1 + 1], bc11 = bp[dirg*32 + 2*p1 + 1];

        if (dirg == 2) {                   // down: rows 0..255, row 0 raw
            float2 xa = unpackh2(g0[0]), xb = unpackh2(g1[0]);
            float h00 = xa.x, h01 = xa.y, h10 = xb.x, h11 = xb.y;
            outq[0] = make_uint2(packh2(h00, h01), packh2(h10, h11));
#pragma unroll 8
            for (int i = 1; i < Hh; i++) {
                float2 a = unpackh2(g0[i*Ww]), c = unpackh2(g1[i*Ww]);
                h00 = fmaxf(fmaf(wc00, h00, a.x + bc00), 0.f);
                h01 = fmaxf(fmaf(wc01, h01, a.y + bc01), 0.f);
                h10 = fmaxf(fmaf(wc10, h10, c.x + bc10), 0.f);
                h11 = fmaxf(fmaf(wc11, h11, c.y + bc11), 0.f);
                outq[i*Ww] = make_uint2(packh2(h00, h01), packh2(h10, h11));
            }
        } else {                           // up: rows 255..0
            float2 xa = unpackh2(g0[(Hh-1)*Ww]), xb = unpackh2(g1[(Hh-1)*Ww]);
            float h00 = xa.x, h01 = xa.y, h10 = xb.x, h11 = xb.y;
            outq[(Hh-1)*Ww] = make_uint2(packh2(h00, h01), packh2(h10, h11));
#pragma unroll 8
            for (int i = Hh - 2; i >= 0; i--) {
                float2 a = unpackh2(g0[i*Ww]), c = unpackh2(g1[i*Ww]);
                h00 = fmaxf(fmaf(wc00, h00, a.x + bc00), 0.f);
                h01 = fmaxf(fmaf(wc01, h01, a.y + bc01), 0.f);
                h10 = fmaxf(fmaf(wc10, h10, c.x + bc10), 0.f);
                h11 = fmaxf(fmaf(wc11, h11, c.y + bc11), 0.f);
                outq[i*Ww] = make_uint2(packh2(h00, h01), packh2(h10, h11));
            }
        }
        return;
    }

    // ---- W scans: blocks 64..127 ----
    int m = blk - 64;
    int dirg = (m >> 5) ? 3 : 1;           // 0..31 => right(1), 32..63 => left(3)
    int n = m & 31;
    int b = b_base + (n >> 3), c1 = (n >> 2) & 1, j = n & 3;
    int p0 = 8*c1 + j, p1 = p0 + 4;
    int t = threadIdx.x;
    const uint32_t* g0 = in + ((size_t)b*16 + p0)*HW;
    const uint32_t* g1 = in + ((size_t)b*16 + p1)*HW;
    uint32_t* gout = outp + ((size_t)(b*32 + (2*dirg + c1)*4 + j))*HW*2;
    const bool rightP = (dirg == 1);
    float wc00 = wp[dirg*32 + 2*p0],     bc00 = bp[dirg*32 + 2*p0];
    float wc01 = wp[dirg*32 + 2*p0 + 1], bc01 = bp[dirg*32 + 2*p0 + 1];
    float wc10 = wp[dirg*32 + 2*p1],     bc10 = bp[dirg*32 + 2*p1];
    float wc11 = wp[dirg*32 + 2*p1 + 1], bc11 = bp[dirg*32 + 2*p1 + 1];
    float h00 = 0.f, h01 = 0.f, h10 = 0.f, h11 = 0.f;
    uint32_t* xs0 = xs;
    uint32_t* xs1 = xs + 8448;

    for (int s = 0; s < 8; s++) {
        int cx = rightP ? s : 7 - s;
#pragma unroll
        for (int k = 0; k < 16; k++) {     // 2 planes x 256 rows x 8 f4
            int tt = t + k*256;
            int pl = tt >> 11;
            int r  = tt & 2047;
            int row = r >> 3, f4 = r & 7;
            const uint32_t* gsrc = pl ? g1 : g0;
            uint4 v = *(const uint4*)(gsrc + row*256 + cx*32 + f4*4);
            uint32_t* dd = (pl ? xs1 : xs0) + row*33 + f4*4;
            dd[0] = v.x; dd[1] = v.y; dd[2] = v.z; dd[3] = v.w;
        }
        __syncthreads();
        {
            uint32_t* r0 = xs0 + t*33;
            uint32_t* r1 = xs1 + t*33;
            {
                int jj = rightP ? 0 : 31;
                float2 a = unpackh2(r0[jj]), c = unpackh2(r1[jj]);
                if (s == 0) { h00 = a.x; h01 = a.y; h10 = c.x; h11 = c.y; }
                else {
                    h00 = fmaxf(fmaf(wc00, h00, a.x + bc00), 0.f);
                    h01 = fmaxf(fmaf(wc01, h01, a.y + bc01), 0.f);
                    h10 = fmaxf(fmaf(wc10, h10, c.x + bc10), 0.f);
                    h11 = fmaxf(fmaf(wc11, h11, c.y + bc11), 0.f);
                }
                r0[jj] = packh2(h00, h01); r1[jj] = packh2(h10, h11);
            }
            if (rightP) {
#pragma unroll
                for (int jj = 1; jj < 32; jj++) {
                    float2 a = unpackh2(r0[jj]), c = unpackh2(r1[jj]);
                    h00 = fmaxf(fmaf(wc00, h00, a.x + bc00), 0.f);
                    h01 = fmaxf(fmaf(wc01, h01, a.y + bc01), 0.f);
                    h10 = fmaxf(fmaf(wc10, h10, c.x + bc10), 0.f);
                    h11 = fmaxf(fmaf(wc11, h11, c.y + bc11), 0.f);
                    r0[jj] = packh2(h00, h01); r1[jj] = packh2(h10, h11);
                }
            } else {
#pragma unroll
                for (int jj = 30; jj >= 0; jj--) {
                    float2 a = unpackh2(r0[jj]), c = unpackh2(r1[jj]);
                    h00 = fmaxf(fmaf(wc00, h00, a.x + bc00), 0.f);
                    h01 = fmaxf(fmaf(wc01, h01, a.y + bc01), 0.f);
                    h10 = fmaxf(fmaf(wc10, h10, c.x + bc10), 0.f);
                    h11 = fmaxf(fmaf(wc11, h11, c.y + bc11), 0.f);
                    r0[jj] = packh2(h00, h01); r1[jj] = packh2(h10, h11);
                }
            }
        }
        __syncthreads();
#pragma unroll
        for (int k = 0; k < 16; k++) {     // 256 rows x 16 uint4 (2 px each)
            int tt = t + k*256;
            int row = tt >> 4, u = tt & 15;
            int px0 = cx*32 + u*2;
            uint4 o;
            o.x = xs0[row*33 + u*2];
            o.y = xs1[row*33 + u*2];
            o.z = xs0[row*33 + u*2 + 1];
            o.w = xs1[row*33 + u*2 + 1];
            *(uint4*)(gout + ((size_t)row*256 + px0)*2) = o;
        }
        __syncthreads();
    }
}

// ---------------------------------------------------------------------------
// Fused kernel: blocks < nScan run one scan unit first, then all blocks drain
// the conv tile pool. Conv: fp16 m16n8k16, tile 128x4, qplane smem layout
// (row stride 296 words -> conflict-free LDS.64 A fragments).
// ---------------------------------------------------------------------------
template<int NQP, int NCH, int OUTMODE>
__global__ void __launch_bounds__(256, 2) fused_kernel(
    const uint32_t* __restrict__ in, const uint32_t* __restrict__ wbuf,
    void* __restrict__ outp, const float* __restrict__ w_out,
    int tileBase, int tileCount, int ctrIdx,
    const uint32_t* __restrict__ scanIn, uint32_t* __restrict__ scanOut,
    const float* __restrict__ swp, const float* __restrict__ sbp,
    int scanB0, int nScan)
{
    constexpr int INW = 6*4*296;       // 7104 words per input buffer
    constexpr int WW  = 9*32*8;        // 2304 words per weight slice
    extern __shared__ float sm[];
    __shared__ int s_tg;

    if ((int)blockIdx.x < nScan)
        scan_body(blockIdx.x, (uint32_t*)sm, scanIn, scanOut, swp, sbp, scanB0);

    float* s_in[3] = { sm, sm + INW, sm + 2*INW };
    float* s_w[3]  = { sm + 3*INW, sm + 3*INW + WW, sm + 3*INW + 2*WW };
    const uint32_t s_in_u[3] = { smem_u32(s_in[0]), smem_u32(s_in[1]), smem_u32(s_in[2]) };
    const uint32_t s_w_u[3]  = { smem_u32(s_w[0]),  smem_u32(s_w[1]),  smem_u32(s_w[2])  };

    const int tid = threadIdx.x;
    const int lane = tid & 31;
    const int wrp = tid >> 5;
    const int r4 = lane >> 2, c4 = lane & 3;
    const int ywarp = wrp >> 1;
    const int xwarp = (wrp & 1) * 64;

    float wo0[4], wo1[4];
    if (OUTMODE == 2) {
#pragma unroll
        for (int nb = 0; nb < 4; nb++) {
            wo0[nb] = __ldg(w_out + nb*8 + c4*2);
            wo1[nb] = __ldg(w_out + nb*8 + c4*2 + 1);
        }
    }

    for (;;) {
        if (tid == 0) s_tg = atomicAdd(&g_ctr[ctrIdx], 1);
        __syncthreads();
        const int tpool = s_tg;
        __syncthreads();
        if (tpool >= tileCount) break;
        const int tg = tileBase + tpool;

        const int b  = tg >> 7;
        const int ty = (tg >> 1) & 63;
        const int tx = tg & 1;
        const int x0 = tx*128, y0 = ty*4;

        auto STAGE = [&](int ch) {
            const int bufi = ch % 3;
            const uint32_t* base = in + ((size_t)b*NQP + ch*4)*(HW*2);
#pragma unroll
            for (int k = 0; k < 7; k++) {
                int t = tid + k*256;
                if (t < 1632) {                    // 6 iy x 4 g x 68 f4
                    int iy = t / 272;
                    int r  = t - iy*272;
                    int g  = r / 68;
                    int f4 = r - g*68;
                    int gy = y0 - 1 + iy;
                    int gxs = x0 - 4 + f4*2;       // 2 pixels per 16B
                    bool pred = ((unsigned)gy < 256u) && ((unsigned)gxs <= 254u);
                    const uint32_t* src = base + (size_t)g*(HW*2)
                                        + (pred ? (gy*256 + gxs)*2 : 0);
                    cp16(s_in_u[bufi] + (((iy*4 + g)*296 + f4*4) << 2), src, pred);
                }
            }
            const uint32_t* wsrc = wbuf + (size_t)ch*WW;
#pragma unroll
            for (int k = 0; k < 3; k++) {
                int t = tid + k*256;
                if (t < 576) cp16(s_w_u[bufi] + (t << 4), wsrc + t*4, true);
            }
            cp_commit();
        };

        float acc[4][4][4];
#pragma unroll
        for (int mb = 0; mb < 4; mb++)
#pragma unroll
            for (int nb = 0; nb < 4; nb++)
#pragma unroll
                for (int q = 0; q < 4; q++) acc[mb][nb][q] = 0.f;

        STAGE(0);
        if (NCH > 1) STAGE(1);

        for (int ch = 0; ch < NCH; ch++) {
            if (ch == NCH - 1) cp_wait<0>(); else cp_wait<1>();
            __syncthreads();
            if (ch + 2 < NCH) STAGE(ch + 2);

            const uint32_t* bufI = (const uint32_t*)s_in[ch % 3];
            const uint32_t* bw   = (const uint32_t*)s_w[ch % 3];
#pragma unroll
            for (int dy = 0; dy < 3; dy++)
#pragma unroll
            for (int dx = 0; dx < 3; dx++) {
                const int tap = dy*3 + dx;
                uint2 A0[4], A1[4];
#pragma unroll
                for (int mb = 0; mb < 4; mb++) {
                    int iy = ywarp + dy;
                    int sx = xwarp + mb*16 + r4 + dx + 3;
                    int b0 = (iy*4 + c4)*296 + 2*sx;
                    A0[mb] = *(const uint2*)(bufI + b0);        // {a0, a2}
                    A1[mb] = *(const uint2*)(bufI + b0 + 16);   // {a1, a3} (+8 px)
                }
#pragma unroll
                for (int nb = 0; nb < 4; nb++) {
                    uint2 bb = *(const uint2*)&bw[((tap*32 + nb*8 + r4) << 3) + c4*2];
#pragma unroll
                    for (int mb = 0; mb < 4; mb++) {
                        asm("mma.sync.aligned.m16n8k16.row.col.f32.f16.f16.f32 "
                            "{%0,%1,%2,%3}, {%4,%5,%6,%7}, {%8,%9}, {%0,%1,%2,%3};"
                            : "+f"(acc[mb][nb][0]), "+f"(acc[mb][nb][1]),
                              "+f"(acc[mb][nb][2]), "+f"(acc[mb][nb][3])
                            : "r"(A0[mb].x), "r"(A1[mb].x),
                              "r"(A0[mb].y), "r"(A1[mb].y),
                              "r"(bb.x), "r"(bb.y));
                    }
                }
            }
        }

        if (OUTMODE == 2) {
            float* outO = (float*)outp + (size_t)b*HW + (y0 + ywarp)*256 + x0;
#pragma unroll
            for (int mb = 0; mb < 4; mb++) {
                int px = xwarp + mb*16 + r4;
                float pp = 0.f, pq = 0.f;
#pragma unroll
                for (int nb = 0; nb < 4; nb++) {
                    pp = fmaf(wo0[nb], fmaxf(acc[mb][nb][0], 0.f), pp);
                    pp = fmaf(wo1[nb], fmaxf(acc[mb][nb][1], 0.f), pp);
                    pq = fmaf(wo0[nb], fmaxf(acc[mb][nb][2], 0.f), pq);
                    pq = fmaf(wo1[nb], fmaxf(acc[mb][nb][3], 0.f), pq);
                }
                pp += __shfl_xor_sync(0xFFFFFFFFu, pp, 1);
                pp += __shfl_xor_sync(0xFFFFFFFFu, pp, 2);
                pq += __shfl_xor_sync(0xFFFFFFFFu, pq, 1);
                pq += __shfl_xor_sync(0xFFFFFFFFu, pq, 2);
                if (c4 == 0) {
                    outO[px]     = 1.f / (1.f + expf(-pp));
                    outO[px + 8] = 1.f / (1.f + expf(-pq));
                }
            }
        } else {
            uint32_t* outP = (uint32_t*)outp;
#pragma unroll
            for (int mb = 0; mb < 4; mb++) {
                int px = xwarp + mb*16 + r4;
#pragma unroll
                for (int nb = 0; nb < 4; nb++) {
                    uint32_t* orow = outP + (size_t)(b*16 + nb*4 + c4)*HW
                                   + (y0 + ywarp)*256 + x0 + px;
                    orow[0] = packh2(acc[mb][nb][0], acc[mb][nb][1]);
                    orow[8] = packh2(acc[mb][nb][2], acc[mb][nb][3]);
                }
            }
        }
        __syncthreads();
    }
}

// ---------------------------------------------------------------------------
extern "C" void kernel_launch(void* const* d_in, const int* in_sizes, int n_in,
                              void* d_out, int out_size)
{
    const float* x     = (const float*)d_in[0];
    const float* w_in  = (const float*)d_in[1];
    const float* w2    = (const float*)d_in[2];
    const float* w3    = (const float*)d_in[3];
    const float* w_out = (const float*)d_in[4];
    const float* i1w   = (const float*)d_in[5];
    const float* i1b   = (const float*)d_in[6];
    const float* i2w   = (const float*)d_in[7];
    const float* i2b   = (const float*)d_in[8];
    float* out = (float*)d_out;

    uint32_t *dXP, *dA, *dB;
    int* dCtr;
    __half *dWin, *dW2, *dW3;
    cudaGetSymbolAddress((void**)&dXP, g_xpk);
    cudaGetSymbolAddress((void**)&dA, g_bufA);
    cudaGetSymbolAddress((void**)&dB, g_bufB);
    cudaGetSymbolAddress((void**)&dCtr, g_ctr);
    cudaGetSymbolAddress((void**)&dWin, g_win_h);
    cudaGetSymbolAddress((void**)&dW2, g_w2_h);
    cudaGetSymbolAddress((void**)&dW3, g_w3_h);

    const int SMEMC = (3*7104 + 3*2304) * 4;   // 112896 B -> 2 CTAs/SM
    cudaFuncSetAttribute((const void*)fused_kernel<8,2,0>,
                         cudaFuncAttributeMaxDynamicSharedMemorySize, SMEMC);
    cudaFuncSetAttribute((const void*)fused_kernel<32,8,0>,
                         cudaFuncAttributeMaxDynamicSharedMemorySize, SMEMC);
    cudaFuncSetAttribute((const void*)fused_kernel<32,8,2>,
                         cudaFuncAttributeMaxDynamicSharedMemorySize, SMEMC);

    cudaMemsetAsync(dCtr, 0, 8*sizeof(int));

    // prologue: pack x (qplane) + all weight preps in one launch
    prologue_kernel<<<8516, 256>>>(x, w_in, w2, w3, dXP, dWin, dW2, dW3);

    // Software-pipelined halves (h0 = tiles 0..511 / b 0..3, h1 = rest).
    // K1: conv_in(h0)
    fused_kernel<8,2,0><<<296, 256, SMEMC>>>(dXP, (const uint32_t*)dWin, dA,
        nullptr, 0, 512, 0, nullptr, nullptr, nullptr, nullptr, 0, 0);
    // K2: conv_in(h1) || scan1(h0)
    fused_kernel<8,2,0><<<296, 256, SMEMC>>>(dXP, (const uint32_t*)dWin, dA,
        nullptr, 512, 512, 1, dA, dB, i1w, i1b, 0, 128);
    // K3: conv2(h0) || scan1(h1)
    fused_kernel<32,8,0><<<296, 256, SMEMC>>>(dB, (const uint32_t*)dW2, dA,
        nullptr, 0, 512, 2, dA, dB, i1w, i1b, 4, 128);
    // K4: conv2(h1) || scan2(h0)
    fused_kernel<32,8,0><<<296, 256, SMEMC>>>(dB, (const uint32_t*)dW2, dA,
        nullptr, 512, 512, 3, dA, dB, i2w, i2b, 0, 128);
    // K5: conv3+out(h0) || scan2(h1)
    fused_kernel<32,8,2><<<296, 256, SMEMC>>>(dB, (const uint32_t*)dW3, out,
        w_out, 0, 512, 4, dA, dB, i2w, i2b, 4, 128);
    // K6: conv3+out(h1)
    fused_kernel<32,8,2><<<296, 256, SMEMC>>>(dB, (const uint32_t*)dW3, out,
        w_out, 512, 512, 5, nullptr, nullptr, nullptr, nullptr, 0, 0);
}